// round 15
// baseline (speedup 1.0000x reference)
#include <cuda_runtime.h>
#include <cstdint>

// Problem constants
#define BB 32
#define NN 8192
#define GG 128
#define MM 8320            // N + G
#define KOUT 512
#define MAXFG 128

#define NBIN_NEG 512
#define NBIN_POS 256
#define NBINS 768          // neg bins [0,512), pos bins [512,768)
#define BCAP 64            // bucket capacity (expected load ~16)

#define CHUNKS 37          // per-batch chunks in k_iou (32*37 = 1184 = 8*148 blocks)
#define CHUNK 225          // ceil(8320/37); 128 threads x up to 2 boxes

#define SORT_SLICES 4      // k_sortemit blocks per batch
#define SE_THREADS 1024
#define SE_WARPS 32
#define SORT_STRIDE (SORT_SLICES * SE_WARPS)    // 128 warps per batch

typedef unsigned long long u64;

// Scratch (no allocations allowed). g_hist/g_done are zero at load; the last
// k_sortemit slice-block per batch re-zeroes g_hist and resets g_done after
// all slices have captured it, so every graph replay sees identical state.
__device__ int g_hist[BB * NBINS];
__device__ int g_done[BB];
__device__ u64 g_bucket[BB * NBINS * BCAP];

__device__ __forceinline__ unsigned int fkey(float f) {
    unsigned int u = __float_as_uint(f);
    return (u & 0x80000000u) ? ~u : (u | 0x80000000u);
}

// Monotone fine binning of the key's high word.
__device__ __forceinline__ int binof(unsigned hi) {
    if (hi < 0x80000000u) return -1;
    float c = __uint_as_float(hi ^ 0x80000000u);
    if (hi >= 0xC0000000u) {
        int t = (int)((c - 2.0f) * (float)NBIN_POS);
        return NBIN_NEG + (t > NBIN_POS - 1 ? NBIN_POS - 1 : t);
    }
    int t = (int)(c * (float)NBIN_NEG);
    return t > NBIN_NEG - 1 ? NBIN_NEG - 1 : t;
}

__device__ __forceinline__ void emit_key(int b, int m, bool pos, bool neg, float nv) {
    float c = pos ? (2.0f + nv) : (neg ? nv : -1.0f);
    unsigned hi = fkey(c);
    u64 key = ((u64)hi << 32) | (u64)(0xFFFFFFFFu - (unsigned)m);
    int bin = binof(hi);
    if (bin >= 0) {
        int slot = atomicAdd(&g_hist[b * NBINS + bin], 1);
        if (slot < BCAP)
            g_bucket[(size_t)(b * NBINS + bin) * BCAP + slot] = key;
    }
}

// ---------------------------------------------------------------------------
// K1: classification only, 2 boxes/thread, one-sided clamp (exact: pos/tie
// outcomes only arise from ih>0 && iw>0 pairs where forms coincide).
// grid = 1184 blocks x 128 threads (8 blocks/SM exactly). No epilogue.
// ---------------------------------------------------------------------------
__global__ __launch_bounds__(128) void k_iou(
    const float4* __restrict__ boxes,   // [B][N]  (ymin,xmin,ymax,xmax)
    const float4* __restrict__ gts,     // [B][G]
    const float*  __restrict__ noise)   // [B][M]
{
    __shared__ float4 sg[GG];    // {gz, -gx, gw, -gy}
    __shared__ float  snga[GG];  // -ga
    const int b     = blockIdx.x / CHUNKS;
    const int chunk = blockIdx.x % CHUNKS;
    const int tid   = threadIdx.x;

    {
        float4 g = gts[b * GG + tid];
        float ga = (g.z - g.x) * (g.w - g.y);
        sg[tid] = make_float4(g.z, -g.x, g.w, -g.y);
        snga[tid] = -ga;
    }
    __syncthreads();

    const int mstart = chunk * CHUNK;
    const int mend   = (mstart + CHUNK < MM) ? (mstart + CHUNK) : MM;
    const int mA = mstart + tid;
    if (mA >= mend) return;
    const int mB = mA + 128;
    const bool vB = mB < mend;

    float4 bxA = (mA < NN) ? boxes[b * NN + mA] : gts[b * GG + (mA - NN)];
    float4 bxB = vB ? ((mB < NN) ? boxes[b * NN + mB] : gts[b * GG + (mB - NN)]) : bxA;
    float nvA = noise[b * MM + mA];
    float nvB = vB ? noise[b * MM + mB] : 0.0f;
    float baA = (bxA.z - bxA.x) * (bxA.w - bxA.y);
    float baB = (bxB.z - bxB.x) * (bxB.w - bxB.y);

    const float zA = bxA.z, nxA = -bxA.x, wA = bxA.w, nyA = -bxA.y;
    const float zB = bxB.z, nxB = -bxB.x, wB = bxB.w, nyB = -bxB.y;
    float uA = -1e30f, uB = -1e30f;

    #pragma unroll 8
    for (int g = 0; g < GG; g++) {
        float4 G = sg[g];
        float nga = snga[g];
        {
            float ih = fminf(zA, G.x) + fminf(nxA, G.y);
            float iw = fminf(wA, G.z) + fminf(nyA, G.w);
            float ia = fmaxf(ih, 0.f) * iw;          // one-sided clamp
            uA = fmaxf(uA, fmaf(3.0f, ia, nga));
        }
        {
            float ih = fminf(zB, G.x) + fminf(nxB, G.y);
            float iw = fminf(wB, G.z) + fminf(nyB, G.w);
            float ia = fmaxf(ih, 0.f) * iw;
            uB = fmaxf(uB, fmaf(3.0f, ia, nga));
        }
    }

    emit_key(b, mA, uA > baA, uA < baA, nvA);
    if (vB) emit_key(b, mB, uB > baB, uB < baB, nvB);
}

// Warp-level bitonic sort, descending, 32 elems (1 per lane).
__device__ __forceinline__ void warp_sort32(u64& v) {
    const int lane = threadIdx.x & 31;
    #pragma unroll
    for (unsigned k = 2; k <= 32; k <<= 1) {
        #pragma unroll
        for (unsigned j = k >> 1; j >= 1; j >>= 1) {
            u64 o = __shfl_xor_sync(0xFFFFFFFFu, v, j);
            bool desc = (lane & k) == 0;
            bool up   = (lane & j) == 0;
            bool keepmax = (up == desc);
            v = keepmax ? (v > o ? v : o) : (v < o ? v : o);
        }
    }
}

// Warp-level bitonic sort, descending, 64 elems (2 per lane: e = 2*lane+s).
__device__ __forceinline__ void warp_sort64(u64& v0, u64& v1) {
    const int lane = threadIdx.x & 31;
    #pragma unroll
    for (unsigned k = 2; k <= 64; k <<= 1) {
        #pragma unroll
        for (unsigned j = k >> 1; j >= 1; j >>= 1) {
            bool desc = (((unsigned)(lane << 1)) & k) == 0;
            if (j == 1) {
                u64 hi2 = v0 > v1 ? v0 : v1;
                u64 lo2 = v0 > v1 ? v1 : v0;
                v0 = desc ? hi2 : lo2;
                v1 = desc ? lo2 : hi2;
            } else {
                unsigned lm = j >> 1;
                u64 o0 = __shfl_xor_sync(0xFFFFFFFFu, v0, lm);
                u64 o1 = __shfl_xor_sync(0xFFFFFFFFu, v1, lm);
                bool up = (lane & lm) == 0;
                bool keepmax = (up == desc);
                v0 = keepmax ? (v0 > o0 ? v0 : o0) : (v0 < o0 ? v0 : o0);
                v1 = keepmax ? (v1 > o1 ? v1 : o1) : (v1 < o1 ? v1 : o1);
            }
        }
    }
}

// Emit one output row j from a sorted key (key always from a valid bucket).
__device__ __forceinline__ void emit_row(
    int b, int j, u64 key,
    const float4* __restrict__ boxes, const float4* __restrict__ gts,
    const int* __restrict__ labels,
    const float4* sgt, const float* sga, float* __restrict__ out)
{
    unsigned hi = (unsigned)(key >> 32);
    unsigned m  = 0xFFFFFFFFu - (unsigned)(key & 0xFFFFFFFFu);
    bool posb = hi >= 0xC0000000u;

    float4 roi = (m < NN) ? boxes[b * NN + m] : gts[b * GG + (m - NN)];
    float4 bt = make_float4(0.f, 0.f, 0.f, 0.f);
    int cls = 0, p2l = 0;
    if (posb) {
        float4 bx = roi;
        float ba = (bx.z - bx.x) * (bx.w - bx.y);
        float bi, bu; int bg = 0;
        {
            float4 gt = sgt[0];
            float ih = fminf(bx.z, gt.z) - fmaxf(bx.x, gt.x);
            float iw = fminf(bx.w, gt.w) - fmaxf(bx.y, gt.y);
            bi = fmaxf(ih, 0.f) * fmaxf(iw, 0.f);
            bu = ba + sga[0] - bi;
        }
        #pragma unroll 4
        for (int g = 1; g < GG; g++) {
            float4 gt = sgt[g];
            float ih = fminf(bx.z, gt.z) - fmaxf(bx.x, gt.x);
            float iw = fminf(bx.w, gt.w) - fmaxf(bx.y, gt.y);
            float ia = fmaxf(ih, 0.f) * fmaxf(iw, 0.f);
            float un = ba + sga[g] - ia;
            if (ia * bu > bi * un) { bi = ia; bu = un; bg = g; }
        }
        bt  = sgt[bg];
        cls = labels[b * GG + bg];
        p2l = bg;
    }

    // out layout: sbox[32,512,4] ++ scls[32,512] ++ rois[32,512,4] ++ sp2l[32,512]
    ((float4*)out)[b * KOUT + j] = bt;
    out[BB * KOUT * 4 + b * KOUT + j] = (float)cls;
    ((float4*)(out + BB * KOUT * 4 + BB * KOUT))[b * KOUT + j] = roi;
    out[BB * KOUT * 4 + BB * KOUT + BB * KOUT * 4 + b * KOUT + j] = (float)p2l;
}

// ---------------------------------------------------------------------------
// K2: fused sort + emit. grid (BB, 4) x 1024 threads, no clusters.
// Loads hist -> smem, ticket-zeroes g_hist (last slice only, no waiting),
// warp-shuffle suffix scan, thresholds, per-warp bucket sorts + direct emit.
// ---------------------------------------------------------------------------
__global__ __launch_bounds__(SE_THREADS) void k_sortemit(
    const float4* __restrict__ boxes,
    const float4* __restrict__ gts,
    const int*    __restrict__ labels,
    float*        __restrict__ out)
{
    __shared__ int h[NBINS];
    __shared__ int suf[NBINS];
    __shared__ int stot[24];
    __shared__ int offs[24];
    __shared__ float4 sgt[GG];
    __shared__ float  sga[GG];
    __shared__ int s_tpos, s_tneg, s_last;
    const int b     = blockIdx.x;
    const int slice = blockIdx.y;
    const int tid   = threadIdx.x;
    const int lane  = tid & 31;
    const int warp  = tid >> 5;

    // Load hist (+ per-warp suffix scan in registers for warps 0..23)
    int sv = 0;
    if (tid < NBINS) {
        int v = g_hist[b * NBINS + tid];
        if (v > BCAP) v = BCAP;
        h[tid] = v;
        sv = v;
        #pragma unroll
        for (int off = 1; off < 32; off <<= 1) {
            int t = __shfl_down_sync(0xFFFFFFFFu, sv, off);
            if (lane + off < 32) sv += t;
        }
        if (lane == 0) stot[warp] = sv;
    }
    if (tid < GG) {
        float4 g = gts[b * GG + tid];
        sgt[tid] = g;
        sga[tid] = (g.z - g.x) * (g.w - g.y);
    }
    if (tid == 0) { s_tpos = NBIN_NEG; s_tneg = 0; }
    __syncthreads();

    // Ticket: last slice to finish loading zeroes g_hist for the next replay.
    if (tid == 0)
        s_last = (atomicAdd(&g_done[b], 1) == SORT_SLICES - 1) ? 1 : 0;

    // Warp 0: cross-warp suffix scan over 24 totals; region split at warp 16.
    if (warp == 0) {
        int t = (lane < 24) ? stot[lane] : 0;
        int mine = t;
        #pragma unroll
        for (int off = 1; off < 32; off <<= 1) {
            int u = __shfl_down_sync(0xFFFFFFFFu, t, off);
            int lim = (lane < 16) ? 16 : 24;   // neg warps [0,16), pos [16,24)
            if (lane + off < lim) t += u;
        }
        if (lane < 24) offs[lane] = t - mine;  // strictly-higher warps in region
    }
    __syncthreads();

    if (s_last) {
        if (tid < NBINS) g_hist[b * NBINS + tid] = 0;
        if (tid == 0) g_done[b] = 0;
    }
    if (tid < NBINS) suf[tid] = sv + offs[warp];
    __syncthreads();

    if (tid < NBINS) {
        bool qual = (tid >= NBIN_NEG) ? (suf[tid] >= MAXFG) : (suf[tid] >= KOUT);
        unsigned mask = __ballot_sync(0xFFFFFFFFu, qual);
        if (qual && (mask >> (lane + 1)) == 0) {
            if (tid >= NBIN_NEG) atomicMax(&s_tpos, tid);
            else                 atomicMax(&s_tneg, tid);
        }
    }
    __syncthreads();

    const int tpos = s_tpos, tneg = s_tneg;
    const int pc      = suf[NBIN_NEG];
    const int negtake = suf[tneg];
    const int nsel    = pc < MAXFG ? pc : MAXFG;
    const int negwin  = KOUT - nsel;          // neg ranks [0, negwin) selected
    const int nposb = NBINS - tpos;
    const int nnegb = NBIN_NEG - tneg;
    const int nb_tot = nposb + nnegb;

    const int gw = slice * SE_WARPS + warp;
    for (int i = gw; i < nb_tot; i += SORT_STRIDE) {
        const bool isPos = (i < nposb);
        const int bin = isPos ? (tpos + i) : (tneg + (i - nposb));
        const int cnt = h[bin];
        if (cnt == 0) continue;
        const int r0 = (bin == NBINS - 1 || bin == NBIN_NEG - 1) ? 0 : suf[bin + 1];
        if (isPos ? (r0 >= nsel) : (r0 >= negwin)) continue;
        const u64* __restrict__ bk = g_bucket + (size_t)(b * NBINS + bin) * BCAP;
        if (cnt <= 32) {
            u64 v = (lane < cnt) ? bk[lane] : 0ULL;
            warp_sort32(v);
            int r = r0 + lane;
            if (lane < cnt) {
                if (isPos) { if (r < nsel) emit_row(b, r, v, boxes, gts, labels, sgt, sga, out); }
                else       { if (r < negwin) emit_row(b, nsel + r, v, boxes, gts, labels, sgt, sga, out); }
            }
        } else {
            u64 v0 = (2 * lane     < cnt) ? bk[2 * lane]     : 0ULL;
            u64 v1 = (2 * lane + 1 < cnt) ? bk[2 * lane + 1] : 0ULL;
            warp_sort64(v0, v1);
            int l0 = 2 * lane, l1 = 2 * lane + 1;
            if (l0 < cnt) {
                int r = r0 + l0;
                if (isPos) { if (r < nsel) emit_row(b, r, v0, boxes, gts, labels, sgt, sga, out); }
                else       { if (r < negwin) emit_row(b, nsel + r, v0, boxes, gts, labels, sgt, sga, out); }
            }
            if (l1 < cnt) {
                int r = r0 + l1;
                if (isPos) { if (r < nsel) emit_row(b, r, v1, boxes, gts, labels, sgt, sga, out); }
                else       { if (r < negwin) emit_row(b, nsel + r, v1, boxes, gts, labels, sgt, sga, out); }
            }
        }
    }

    // Zero-fill any unused tail rows (slice 0 only).
    if (slice == 0) {
        int navail = negtake < negwin ? negtake : negwin;
        int filled = nsel + navail;
        for (int j = filled + tid; j < KOUT; j += SE_THREADS) {
            ((float4*)out)[b * KOUT + j] = make_float4(0.f, 0.f, 0.f, 0.f);
            out[BB * KOUT * 4 + b * KOUT + j] = 0.f;
            ((float4*)(out + BB * KOUT * 4 + BB * KOUT))[b * KOUT + j] =
                make_float4(0.f, 0.f, 0.f, 0.f);
            out[BB * KOUT * 4 + BB * KOUT + BB * KOUT * 4 + b * KOUT + j] = 0.f;
        }
    }
}

extern "C" void kernel_launch(void* const* d_in, const int* in_sizes, int n_in,
                              void* d_out, int out_size) {
    const float4* boxes  = (const float4*)d_in[0];
    const float4* gts    = (const float4*)d_in[1];
    const int*    labels = (const int*)d_in[2];
    const float*  noise  = (const float*)d_in[3];
    float* out = (float*)d_out;

    k_iou<<<BB * CHUNKS, 128>>>(boxes, gts, noise);
    k_sortemit<<<dim3(BB, SORT_SLICES), SE_THREADS>>>(boxes, gts, labels, out);
}

// round 16
// speedup vs baseline: 1.2653x; 1.2653x over previous
#include <cuda_runtime.h>
#include <cstdint>

// Problem constants
#define BB 32
#define NN 8192
#define GG 128
#define MM 8320            // N + G
#define KOUT 512
#define MAXFG 128

#define NBIN_NEG 512
#define NBIN_POS 256
#define NBINS 768          // neg bins [0,512), pos bins [512,768)
#define BCAP 64            // bucket capacity (expected load ~16)

#define IB_CHUNKS 130      // chunks per batch: 130 x 64 = 8320 exactly
#define IB_BOX 64          // boxes per chunk (32 threads x 2 boxes, no padding)

#define SORT_SLICES 8
#define SORT_WARPS 24      // 768 threads
#define SORT_STRIDE (SORT_SLICES * SORT_WARPS)   // 192 warps per batch

typedef unsigned long long u64;

// Scratch (no allocations allowed). g_hist/g_done are zero at load; the last
// k_iou block per batch snapshots hist into g_hist2, zeroes g_hist and resets
// g_done, so every graph replay sees identical initial state.
__device__ int g_hist[BB * NBINS];
__device__ int g_hist2[BB * NBINS];
__device__ int g_done[BB];
__device__ u64 g_bucket[BB * NBINS * BCAP];

__device__ __forceinline__ unsigned int fkey(float f) {
    unsigned int u = __float_as_uint(f);
    return (u & 0x80000000u) ? ~u : (u | 0x80000000u);
}

// Monotone fine binning of the key's high word.
__device__ __forceinline__ int binof(unsigned hi) {
    if (hi < 0x80000000u) return -1;
    float c = __uint_as_float(hi ^ 0x80000000u);
    if (hi >= 0xC0000000u) {
        int t = (int)((c - 2.0f) * (float)NBIN_POS);
        return NBIN_NEG + (t > NBIN_POS - 1 ? NBIN_POS - 1 : t);
    }
    int t = (int)(c * (float)NBIN_NEG);
    return t > NBIN_NEG - 1 ? NBIN_NEG - 1 : t;
}

__device__ __forceinline__ void emit_key(int b, int m, bool pos, bool neg, float nv) {
    float c = pos ? (2.0f + nv) : (neg ? nv : -1.0f);
    unsigned hi = fkey(c);
    u64 key = ((u64)hi << 32) | (u64)(0xFFFFFFFFu - (unsigned)m);
    int bin = binof(hi);
    if (bin >= 0) {
        int slot = atomicAdd(&g_hist[b * NBINS + bin], 1);
        if (slot < BCAP)
            g_bucket[(size_t)(b * NBINS + bin) * BCAP + slot] = key;
    }
}

// ---------------------------------------------------------------------------
// K1: classification only. ONE WARP per block, 64 boxes per block: 130x64 =
// 8320 exactly -> zero lane padding, no validity branches. Inner math is
// byte-identical to the R13 kernel (one-sided clamp; exact classification).
// grid = 32*130 = 4160 blocks x 32 threads (28-29 blocks/SM).
// Last block per batch snapshots hist -> hist2 and zeroes hist.
// ---------------------------------------------------------------------------
__global__ __launch_bounds__(32) void k_iou(
    const float4* __restrict__ boxes,   // [B][N]  (ymin,xmin,ymax,xmax)
    const float4* __restrict__ gts,     // [B][G]
    const float*  __restrict__ noise)   // [B][M]
{
    __shared__ float4 sg[GG];    // {gz, -gx, gw, -gy}
    __shared__ float  snga[GG];  // -ga
    const int b     = blockIdx.x / IB_CHUNKS;
    const int chunk = blockIdx.x % IB_CHUNKS;
    const int tid   = threadIdx.x;

    #pragma unroll
    for (int i = tid; i < GG; i += 32) {
        float4 g = gts[b * GG + i];
        float ga = (g.z - g.x) * (g.w - g.y);
        sg[i] = make_float4(g.z, -g.x, g.w, -g.y);
        snga[i] = -ga;
    }
    __syncwarp();

    const int mA = chunk * IB_BOX + tid;
    const int mB = mA + 32;

    float4 bxA = (mA < NN) ? boxes[b * NN + mA] : gts[b * GG + (mA - NN)];
    float4 bxB = (mB < NN) ? boxes[b * NN + mB] : gts[b * GG + (mB - NN)];
    float nvA = noise[b * MM + mA];
    float nvB = noise[b * MM + mB];
    float baA = (bxA.z - bxA.x) * (bxA.w - bxA.y);
    float baB = (bxB.z - bxB.x) * (bxB.w - bxB.y);

    const float zA = bxA.z, nxA = -bxA.x, wA = bxA.w, nyA = -bxA.y;
    const float zB = bxB.z, nxB = -bxB.x, wB = bxB.w, nyB = -bxB.y;
    float uA = -1e30f, uB = -1e30f;

    #pragma unroll 8
    for (int g = 0; g < GG; g++) {
        float4 G = sg[g];
        float nga = snga[g];
        {
            float ih = fminf(zA, G.x) + fminf(nxA, G.y);
            float iw = fminf(wA, G.z) + fminf(nyA, G.w);
            float ia = fmaxf(ih, 0.f) * iw;          // one-sided clamp
            uA = fmaxf(uA, fmaf(3.0f, ia, nga));
        }
        {
            float ih = fminf(zB, G.x) + fminf(nxB, G.y);
            float iw = fminf(wB, G.z) + fminf(nyB, G.w);
            float ia = fmaxf(ih, 0.f) * iw;
            uB = fmaxf(uB, fmaf(3.0f, ia, nga));
        }
    }

    emit_key(b, mA, uA > baA, uA < baA, nvA);
    emit_key(b, mB, uB > baB, uB < baB, nvB);

    // Last-block-per-batch: snapshot hist -> hist2, zero hist for next replay.
    __threadfence();
    __syncwarp();
    unsigned tk = 0;
    if (tid == 0) tk = atomicAdd(&g_done[b], 1);
    tk = __shfl_sync(0xFFFFFFFFu, tk, 0);
    if (tk == IB_CHUNKS - 1) {
        #pragma unroll
        for (int i = tid; i < NBINS; i += 32) {
            int v = __ldcg(&g_hist[b * NBINS + i]);
            g_hist2[b * NBINS + i] = v;
            g_hist[b * NBINS + i] = 0;
        }
        if (tid == 0) g_done[b] = 0;
    }
}

// Warp-level bitonic sort, descending, 32 elems (1 per lane).
__device__ __forceinline__ void warp_sort32(u64& v) {
    const int lane = threadIdx.x & 31;
    #pragma unroll
    for (unsigned k = 2; k <= 32; k <<= 1) {
        #pragma unroll
        for (unsigned j = k >> 1; j >= 1; j >>= 1) {
            u64 o = __shfl_xor_sync(0xFFFFFFFFu, v, j);
            bool desc = (lane & k) == 0;
            bool up   = (lane & j) == 0;
            bool keepmax = (up == desc);
            v = keepmax ? (v > o ? v : o) : (v < o ? v : o);
        }
    }
}

// Warp-level bitonic sort, descending, 64 elems (2 per lane: e = 2*lane+s).
__device__ __forceinline__ void warp_sort64(u64& v0, u64& v1) {
    const int lane = threadIdx.x & 31;
    #pragma unroll
    for (unsigned k = 2; k <= 64; k <<= 1) {
        #pragma unroll
        for (unsigned j = k >> 1; j >= 1; j >>= 1) {
            bool desc = (((unsigned)(lane << 1)) & k) == 0;
            if (j == 1) {
                u64 hi2 = v0 > v1 ? v0 : v1;
                u64 lo2 = v0 > v1 ? v1 : v0;
                v0 = desc ? hi2 : lo2;
                v1 = desc ? lo2 : hi2;
            } else {
                unsigned lm = j >> 1;
                u64 o0 = __shfl_xor_sync(0xFFFFFFFFu, v0, lm);
                u64 o1 = __shfl_xor_sync(0xFFFFFFFFu, v1, lm);
                bool up = (lane & lm) == 0;
                bool keepmax = (up == desc);
                v0 = keepmax ? (v0 > o0 ? v0 : o0) : (v0 < o0 ? v0 : o0);
                v1 = keepmax ? (v1 > o1 ? v1 : o1) : (v1 < o1 ? v1 : o1);
            }
        }
    }
}

// Emit one output row j from a sorted key (key always from a valid bucket).
__device__ __forceinline__ void emit_row(
    int b, int j, u64 key,
    const float4* __restrict__ boxes, const float4* __restrict__ gts,
    const int* __restrict__ labels,
    const float4* sgt, const float* sga, float* __restrict__ out)
{
    unsigned hi = (unsigned)(key >> 32);
    unsigned m  = 0xFFFFFFFFu - (unsigned)(key & 0xFFFFFFFFu);
    bool posb = hi >= 0xC0000000u;

    float4 roi = (m < NN) ? boxes[b * NN + m] : gts[b * GG + (m - NN)];
    float4 bt = make_float4(0.f, 0.f, 0.f, 0.f);
    int cls = 0, p2l = 0;
    if (posb) {
        float4 bx = roi;
        float ba = (bx.z - bx.x) * (bx.w - bx.y);
        float bi, bu; int bg = 0;
        {
            float4 gt = sgt[0];
            float ih = fminf(bx.z, gt.z) - fmaxf(bx.x, gt.x);
            float iw = fminf(bx.w, gt.w) - fmaxf(bx.y, gt.y);
            bi = fmaxf(ih, 0.f) * fmaxf(iw, 0.f);
            bu = ba + sga[0] - bi;
        }
        #pragma unroll 4
        for (int g = 1; g < GG; g++) {
            float4 gt = sgt[g];
            float ih = fminf(bx.z, gt.z) - fmaxf(bx.x, gt.x);
            float iw = fminf(bx.w, gt.w) - fmaxf(bx.y, gt.y);
            float ia = fmaxf(ih, 0.f) * fmaxf(iw, 0.f);
            float un = ba + sga[g] - ia;
            if (ia * bu > bi * un) { bi = ia; bu = un; bg = g; }
        }
        bt  = sgt[bg];
        cls = labels[b * GG + bg];
        p2l = bg;
    }

    // out layout: sbox[32,512,4] ++ scls[32,512] ++ rois[32,512,4] ++ sp2l[32,512]
    ((float4*)out)[b * KOUT + j] = bt;
    out[BB * KOUT * 4 + b * KOUT + j] = (float)cls;
    ((float4*)(out + BB * KOUT * 4 + BB * KOUT))[b * KOUT + j] = roi;
    out[BB * KOUT * 4 + BB * KOUT + BB * KOUT * 4 + b * KOUT + j] = (float)p2l;
}

// ---------------------------------------------------------------------------
// K2: fused sort + emit, NO clusters (byte-identical to the R13 kernel).
// grid (BB, 8) x 768 threads. Each slice reads the hist snapshot, recomputes
// scan + thresholds, sorts its share of the selected buckets and emits rows.
// ---------------------------------------------------------------------------
__global__ __launch_bounds__(768) void k_sortemit(
    const float4* __restrict__ boxes,
    const float4* __restrict__ gts,
    const int*    __restrict__ labels,
    float*        __restrict__ out)
{
    __shared__ int h[NBINS];
    __shared__ int suf[NBINS];
    __shared__ float4 sgt[GG];
    __shared__ float  sga[GG];
    __shared__ int s_tpos, s_tneg;
    const int b     = blockIdx.x;
    const int slice = blockIdx.y;
    const int tid   = threadIdx.x;
    const int lane  = tid & 31;
    const int warp  = tid >> 5;

    if (tid < NBINS) {
        int v = g_hist2[b * NBINS + tid];
        if (v > BCAP) v = BCAP;
        h[tid] = v;
        suf[tid] = v;
    }
    if (tid < GG) {
        float4 g = gts[b * GG + tid];
        sgt[tid] = g;
        sga[tid] = (g.z - g.x) * (g.w - g.y);
    }
    if (tid == 0) { s_tpos = NBIN_NEG; s_tneg = 0; }
    __syncthreads();

    // Region-masked suffix scan (neg [0,512), pos [512,768))
    #pragma unroll
    for (int d = 1; d < NBIN_NEG; d <<= 1) {
        int add = 0;
        if (tid < NBINS) {
            int e = (tid < NBIN_NEG) ? NBIN_NEG : NBINS;
            if (tid + d < e) add = suf[tid + d];
        }
        __syncthreads();
        if (tid < NBINS) suf[tid] += add;
        __syncthreads();
    }

    if (tid < NBINS) {
        bool qual = (tid >= NBIN_NEG) ? (suf[tid] >= MAXFG) : (suf[tid] >= KOUT);
        unsigned mask = __ballot_sync(0xFFFFFFFFu, qual);
        if (qual && (mask >> (lane + 1)) == 0) {
            if (tid >= NBIN_NEG) atomicMax(&s_tpos, tid);
            else                 atomicMax(&s_tneg, tid);
        }
    }
    __syncthreads();

    const int tpos = s_tpos, tneg = s_tneg;
    const int pc      = suf[NBIN_NEG];
    const int negtake = suf[tneg];
    const int nsel    = pc < MAXFG ? pc : MAXFG;
    const int negwin  = KOUT - nsel;          // neg ranks [0, negwin) selected
    const int nposb = NBINS - tpos;
    const int nnegb = NBIN_NEG - tneg;
    const int nb_tot = nposb + nnegb;

    const int gw = slice * SORT_WARPS + warp;
    for (int i = gw; i < nb_tot; i += SORT_STRIDE) {
        const bool isPos = (i < nposb);
        const int bin = isPos ? (tpos + i) : (tneg + (i - nposb));
        const int cnt = h[bin];
        if (cnt == 0) continue;
        const int r0 = (bin == NBINS - 1 || bin == NBIN_NEG - 1) ? 0 : suf[bin + 1];
        if (isPos ? (r0 >= nsel) : (r0 >= negwin)) continue;
        const u64* __restrict__ bk = g_bucket + (size_t)(b * NBINS + bin) * BCAP;
        if (cnt <= 32) {
            u64 v = (lane < cnt) ? bk[lane] : 0ULL;
            warp_sort32(v);
            int r = r0 + lane;
            if (lane < cnt) {
                if (isPos) { if (r < nsel) emit_row(b, r, v, boxes, gts, labels, sgt, sga, out); }
                else       { if (r < negwin) emit_row(b, nsel + r, v, boxes, gts, labels, sgt, sga, out); }
            }
        } else {
            u64 v0 = (2 * lane     < cnt) ? bk[2 * lane]     : 0ULL;
            u64 v1 = (2 * lane + 1 < cnt) ? bk[2 * lane + 1] : 0ULL;
            warp_sort64(v0, v1);
            int l0 = 2 * lane, l1 = 2 * lane + 1;
            if (l0 < cnt) {
                int r = r0 + l0;
                if (isPos) { if (r < nsel) emit_row(b, r, v0, boxes, gts, labels, sgt, sga, out); }
                else       { if (r < negwin) emit_row(b, nsel + r, v0, boxes, gts, labels, sgt, sga, out); }
            }
            if (l1 < cnt) {
                int r = r0 + l1;
                if (isPos) { if (r < nsel) emit_row(b, r, v1, boxes, gts, labels, sgt, sga, out); }
                else       { if (r < negwin) emit_row(b, nsel + r, v1, boxes, gts, labels, sgt, sga, out); }
            }
        }
    }

    // Zero-fill any unused tail rows (slice 0 only).
    if (slice == 0) {
        int navail = negtake < negwin ? negtake : negwin;
        int filled = nsel + navail;
        for (int j = filled + tid; j < KOUT; j += 768) {
            ((float4*)out)[b * KOUT + j] = make_float4(0.f, 0.f, 0.f, 0.f);
            out[BB * KOUT * 4 + b * KOUT + j] = 0.f;
            ((float4*)(out + BB * KOUT * 4 + BB * KOUT))[b * KOUT + j] =
                make_float4(0.f, 0.f, 0.f, 0.f);
            out[BB * KOUT * 4 + BB * KOUT + BB * KOUT * 4 + b * KOUT + j] = 0.f;
        }
    }
}

extern "C" void kernel_launch(void* const* d_in, const int* in_sizes, int n_in,
                              void* d_out, int out_size) {
    const float4* boxes  = (const float4*)d_in[0];
    const float4* gts    = (const float4*)d_in[1];
    const int*    labels = (const int*)d_in[2];
    const float*  noise  = (const float*)d_in[3];
    float* out = (float*)d_out;

    k_iou<<<BB * IB_CHUNKS, 32>>>(boxes, gts, noise);
    k_sortemit<<<dim3(BB, SORT_SLICES), 768>>>(boxes, gts, labels, out);
}

// round 17
// speedup vs baseline: 1.4198x; 1.1221x over previous
#include <cuda_runtime.h>
#include <cstdint>

// Problem constants
#define BB 32
#define NN 8192
#define GG 128
#define MM 8320            // N + G
#define KOUT 512
#define MAXFG 128

#define NBIN_NEG 512
#define NBIN_POS 256
#define NBINS 768          // neg bins [0,512), pos bins [512,768)
#define BCAP 64            // bucket capacity (expected load ~16)

#define CHUNKS 37          // per-batch chunks in k_iou (32*37 = 1184 = 8*148 blocks)
#define CHUNK 225          // ceil(8320/37); 128 threads x up to 2 boxes

#define SORT_SLICES 8
#define SORT_WARPS 24      // 768 threads
#define SORT_STRIDE (SORT_SLICES * SORT_WARPS)   // 192 warps per batch

typedef unsigned long long u64;

// Scratch (no allocations allowed). g_hist/g_done are zero at load; the last
// k_iou block per batch snapshots hist into g_hist2, zeroes g_hist and resets
// g_done, so every graph replay sees identical initial state.
__device__ int g_hist[BB * NBINS];
__device__ int g_hist2[BB * NBINS];
__device__ int g_done[BB];
__device__ u64 g_bucket[BB * NBINS * BCAP];

__device__ __forceinline__ unsigned int fkey(float f) {
    unsigned int u = __float_as_uint(f);
    return (u & 0x80000000u) ? ~u : (u | 0x80000000u);
}

// Monotone fine binning of the key's high word.
__device__ __forceinline__ int binof(unsigned hi) {
    if (hi < 0x80000000u) return -1;
    float c = __uint_as_float(hi ^ 0x80000000u);
    if (hi >= 0xC0000000u) {
        int t = (int)((c - 2.0f) * (float)NBIN_POS);
        return NBIN_NEG + (t > NBIN_POS - 1 ? NBIN_POS - 1 : t);
    }
    int t = (int)(c * (float)NBIN_NEG);
    return t > NBIN_NEG - 1 ? NBIN_NEG - 1 : t;
}

__device__ __forceinline__ void emit_key(int b, int m, bool pos, bool neg, float nv) {
    float c = pos ? (2.0f + nv) : (neg ? nv : -1.0f);
    unsigned hi = fkey(c);
    u64 key = ((u64)hi << 32) | (u64)(0xFFFFFFFFu - (unsigned)m);
    int bin = binof(hi);
    if (bin >= 0) {
        int slot = atomicAdd(&g_hist[b * NBINS + bin], 1);
        if (slot < BCAP)
            g_bucket[(size_t)(b * NBINS + bin) * BCAP + slot] = key;
    }
}

// ---------------------------------------------------------------------------
// K1: classification only, 2 boxes/thread, one-sided clamp (exact: pos/tie
// outcomes only arise from ih>0 && iw>0 pairs where forms coincide).
// Last block per batch snapshots hist -> hist2 and zeroes hist.
// grid = 1184 blocks x 128 threads (8 blocks/SM exactly).
// ---------------------------------------------------------------------------
__global__ __launch_bounds__(128) void k_iou(
    const float4* __restrict__ boxes,   // [B][N]  (ymin,xmin,ymax,xmax)
    const float4* __restrict__ gts,     // [B][G]
    const float*  __restrict__ noise)   // [B][M]
{
    __shared__ float4 sg[GG];    // {gz, -gx, gw, -gy}
    __shared__ float  snga[GG];  // -ga
    __shared__ int s_last;
    const int b     = blockIdx.x / CHUNKS;
    const int chunk = blockIdx.x % CHUNKS;
    const int tid   = threadIdx.x;

    {
        float4 g = gts[b * GG + tid];
        float ga = (g.z - g.x) * (g.w - g.y);
        sg[tid] = make_float4(g.z, -g.x, g.w, -g.y);
        snga[tid] = -ga;
    }
    __syncthreads();

    const int mstart = chunk * CHUNK;
    const int mend   = (mstart + CHUNK < MM) ? (mstart + CHUNK) : MM;
    const int mA = mstart + tid;
    const int mB = mA + 128;
    const bool vA = mA < mend;
    const bool vB = mB < mend;

    if (vA) {
        float4 bxA = (mA < NN) ? boxes[b * NN + mA] : gts[b * GG + (mA - NN)];
        float4 bxB = vB ? ((mB < NN) ? boxes[b * NN + mB] : gts[b * GG + (mB - NN)]) : bxA;
        float nvA = noise[b * MM + mA];
        float nvB = vB ? noise[b * MM + mB] : 0.0f;
        float baA = (bxA.z - bxA.x) * (bxA.w - bxA.y);
        float baB = (bxB.z - bxB.x) * (bxB.w - bxB.y);

        const float zA = bxA.z, nxA = -bxA.x, wA = bxA.w, nyA = -bxA.y;
        const float zB = bxB.z, nxB = -bxB.x, wB = bxB.w, nyB = -bxB.y;
        float uA = -1e30f, uB = -1e30f;

        #pragma unroll 8
        for (int g = 0; g < GG; g++) {
            float4 G = sg[g];
            float nga = snga[g];
            {
                float ih = fminf(zA, G.x) + fminf(nxA, G.y);
                float iw = fminf(wA, G.z) + fminf(nyA, G.w);
                float ia = fmaxf(ih, 0.f) * iw;          // one-sided clamp
                uA = fmaxf(uA, fmaf(3.0f, ia, nga));
            }
            {
                float ih = fminf(zB, G.x) + fminf(nxB, G.y);
                float iw = fminf(wB, G.z) + fminf(nyB, G.w);
                float ia = fmaxf(ih, 0.f) * iw;
                uB = fmaxf(uB, fmaf(3.0f, ia, nga));
            }
        }

        emit_key(b, mA, uA > baA, uA < baA, nvA);
        if (vB) emit_key(b, mB, uB > baB, uB < baB, nvB);
    }

    // Last-block-per-batch: snapshot hist -> hist2, zero hist for next replay.
    __threadfence();
    __syncthreads();
    if (tid == 0)
        s_last = (atomicAdd(&g_done[b], 1) == CHUNKS - 1) ? 1 : 0;
    __syncthreads();
    if (s_last) {
        for (int i = tid; i < NBINS; i += 128) {
            int v = __ldcg(&g_hist[b * NBINS + i]);
            g_hist2[b * NBINS + i] = v;
            g_hist[b * NBINS + i] = 0;
        }
        if (tid == 0) g_done[b] = 0;
    }
}

// Warp-level bitonic sort, descending, 32 elems (1 per lane).
__device__ __forceinline__ void warp_sort32(u64& v) {
    const int lane = threadIdx.x & 31;
    #pragma unroll
    for (unsigned k = 2; k <= 32; k <<= 1) {
        #pragma unroll
        for (unsigned j = k >> 1; j >= 1; j >>= 1) {
            u64 o = __shfl_xor_sync(0xFFFFFFFFu, v, j);
            bool desc = (lane & k) == 0;
            bool up   = (lane & j) == 0;
            bool keepmax = (up == desc);
            v = keepmax ? (v > o ? v : o) : (v < o ? v : o);
        }
    }
}

// Warp-level bitonic sort, descending, 64 elems (2 per lane: e = 2*lane+s).
__device__ __forceinline__ void warp_sort64(u64& v0, u64& v1) {
    const int lane = threadIdx.x & 31;
    #pragma unroll
    for (unsigned k = 2; k <= 64; k <<= 1) {
        #pragma unroll
        for (unsigned j = k >> 1; j >= 1; j >>= 1) {
            bool desc = (((unsigned)(lane << 1)) & k) == 0;
            if (j == 1) {
                u64 hi2 = v0 > v1 ? v0 : v1;
                u64 lo2 = v0 > v1 ? v1 : v0;
                v0 = desc ? hi2 : lo2;
                v1 = desc ? lo2 : hi2;
            } else {
                unsigned lm = j >> 1;
                u64 o0 = __shfl_xor_sync(0xFFFFFFFFu, v0, lm);
                u64 o1 = __shfl_xor_sync(0xFFFFFFFFu, v1, lm);
                bool up = (lane & lm) == 0;
                bool keepmax = (up == desc);
                v0 = keepmax ? (v0 > o0 ? v0 : o0) : (v0 < o0 ? v0 : o0);
                v1 = keepmax ? (v1 > o1 ? v1 : o1) : (v1 < o1 ? v1 : o1);
            }
        }
    }
}

// Emit one output row j from a sorted key (key always from a valid bucket).
__device__ __forceinline__ void emit_row(
    int b, int j, u64 key,
    const float4* __restrict__ boxes, const float4* __restrict__ gts,
    const int* __restrict__ labels,
    const float4* sgt, const float* sga, float* __restrict__ out)
{
    unsigned hi = (unsigned)(key >> 32);
    unsigned m  = 0xFFFFFFFFu - (unsigned)(key & 0xFFFFFFFFu);
    bool posb = hi >= 0xC0000000u;

    float4 roi = (m < NN) ? boxes[b * NN + m] : gts[b * GG + (m - NN)];
    float4 bt = make_float4(0.f, 0.f, 0.f, 0.f);
    int cls = 0, p2l = 0;
    if (posb) {
        float4 bx = roi;
        float ba = (bx.z - bx.x) * (bx.w - bx.y);
        float bi, bu; int bg = 0;
        {
            float4 gt = sgt[0];
            float ih = fminf(bx.z, gt.z) - fmaxf(bx.x, gt.x);
            float iw = fminf(bx.w, gt.w) - fmaxf(bx.y, gt.y);
            bi = fmaxf(ih, 0.f) * fmaxf(iw, 0.f);
            bu = ba + sga[0] - bi;
        }
        #pragma unroll 4
        for (int g = 1; g < GG; g++) {
            float4 gt = sgt[g];
            float ih = fminf(bx.z, gt.z) - fmaxf(bx.x, gt.x);
            float iw = fminf(bx.w, gt.w) - fmaxf(bx.y, gt.y);
            float ia = fmaxf(ih, 0.f) * fmaxf(iw, 0.f);
            float un = ba + sga[g] - ia;
            if (ia * bu > bi * un) { bi = ia; bu = un; bg = g; }
        }
        bt  = sgt[bg];
        cls = labels[b * GG + bg];
        p2l = bg;
    }

    // out layout: sbox[32,512,4] ++ scls[32,512] ++ rois[32,512,4] ++ sp2l[32,512]
    ((float4*)out)[b * KOUT + j] = bt;
    out[BB * KOUT * 4 + b * KOUT + j] = (float)cls;
    ((float4*)(out + BB * KOUT * 4 + BB * KOUT))[b * KOUT + j] = roi;
    out[BB * KOUT * 4 + BB * KOUT + BB * KOUT * 4 + b * KOUT + j] = (float)p2l;
}

// ---------------------------------------------------------------------------
// K2: fused sort + emit, NO clusters. grid (BB, 8) x 768 threads.
// Identical to the 33.28us kernel except the suffix scan: warp-shuffle scan
// (4 block barriers) replaces the 18-barrier Hillis-Steele.
// ---------------------------------------------------------------------------
__global__ __launch_bounds__(768) void k_sortemit(
    const float4* __restrict__ boxes,
    const float4* __restrict__ gts,
    const int*    __restrict__ labels,
    float*        __restrict__ out)
{
    __shared__ int h[NBINS];
    __shared__ int suf[NBINS];
    __shared__ int stot[SORT_WARPS];
    __shared__ int offs[SORT_WARPS];
    __shared__ float4 sgt[GG];
    __shared__ float  sga[GG];
    __shared__ int s_tpos, s_tneg;
    const int b     = blockIdx.x;
    const int slice = blockIdx.y;
    const int tid   = threadIdx.x;
    const int lane  = tid & 31;
    const int warp  = tid >> 5;

    // Load hist + per-warp suffix scan in registers (warp w owns bins [32w,32w+32))
    int v = g_hist2[b * NBINS + tid];
    if (v > BCAP) v = BCAP;
    h[tid] = v;
    int sv = v;
    #pragma unroll
    for (int off = 1; off < 32; off <<= 1) {
        int t = __shfl_down_sync(0xFFFFFFFFu, sv, off);
        if (lane + off < 32) sv += t;
    }
    if (lane == 0) stot[warp] = sv;
    if (tid < GG) {
        float4 g = gts[b * GG + tid];
        sgt[tid] = g;
        sga[tid] = (g.z - g.x) * (g.w - g.y);
    }
    if (tid == 0) { s_tpos = NBIN_NEG; s_tneg = 0; }
    __syncthreads();

    // Warp 0: cross-warp suffix scan over 24 totals; region split at warp 16.
    if (warp == 0) {
        int t = (lane < SORT_WARPS) ? stot[lane] : 0;
        int mine = t;
        #pragma unroll
        for (int off = 1; off < 32; off <<= 1) {
            int u = __shfl_down_sync(0xFFFFFFFFu, t, off);
            int lim = (lane < 16) ? 16 : SORT_WARPS;  // neg warps [0,16), pos [16,24)
            if (lane + off < lim) t += u;
        }
        if (lane < SORT_WARPS) offs[lane] = t - mine; // strictly-higher warps in region
    }
    __syncthreads();

    suf[tid] = sv + offs[warp];
    __syncthreads();

    {
        bool qual = (tid >= NBIN_NEG) ? (suf[tid] >= MAXFG) : (suf[tid] >= KOUT);
        unsigned mask = __ballot_sync(0xFFFFFFFFu, qual);
        if (qual && (mask >> (lane + 1)) == 0) {
            if (tid >= NBIN_NEG) atomicMax(&s_tpos, tid);
            else                 atomicMax(&s_tneg, tid);
        }
    }
    __syncthreads();

    const int tpos = s_tpos, tneg = s_tneg;
    const int pc      = suf[NBIN_NEG];
    const int negtake = suf[tneg];
    const int nsel    = pc < MAXFG ? pc : MAXFG;
    const int negwin  = KOUT - nsel;          // neg ranks [0, negwin) selected
    const int nposb = NBINS - tpos;
    const int nnegb = NBIN_NEG - tneg;
    const int nb_tot = nposb + nnegb;

    const int gw = slice * SORT_WARPS + warp;
    for (int i = gw; i < nb_tot; i += SORT_STRIDE) {
        const bool isPos = (i < nposb);
        const int bin = isPos ? (tpos + i) : (tneg + (i - nposb));
        const int cnt = h[bin];
        if (cnt == 0) continue;
        const int r0 = (bin == NBINS - 1 || bin == NBIN_NEG - 1) ? 0 : suf[bin + 1];
        if (isPos ? (r0 >= nsel) : (r0 >= negwin)) continue;
        const u64* __restrict__ bk = g_bucket + (size_t)(b * NBINS + bin) * BCAP;
        if (cnt <= 32) {
            u64 x = (lane < cnt) ? bk[lane] : 0ULL;
            warp_sort32(x);
            int r = r0 + lane;
            if (lane < cnt) {
                if (isPos) { if (r < nsel) emit_row(b, r, x, boxes, gts, labels, sgt, sga, out); }
                else       { if (r < negwin) emit_row(b, nsel + r, x, boxes, gts, labels, sgt, sga, out); }
            }
        } else {
            u64 v0 = (2 * lane     < cnt) ? bk[2 * lane]     : 0ULL;
            u64 v1 = (2 * lane + 1 < cnt) ? bk[2 * lane + 1] : 0ULL;
            warp_sort64(v0, v1);
            int l0 = 2 * lane, l1 = 2 * lane + 1;
            if (l0 < cnt) {
                int r = r0 + l0;
                if (isPos) { if (r < nsel) emit_row(b, r, v0, boxes, gts, labels, sgt, sga, out); }
                else       { if (r < negwin) emit_row(b, nsel + r, v0, boxes, gts, labels, sgt, sga, out); }
            }
            if (l1 < cnt) {
                int r = r0 + l1;
                if (isPos) { if (r < nsel) emit_row(b, r, v1, boxes, gts, labels, sgt, sga, out); }
                else       { if (r < negwin) emit_row(b, nsel + r, v1, boxes, gts, labels, sgt, sga, out); }
            }
        }
    }

    // Zero-fill any unused tail rows (slice 0 only).
    if (slice == 0) {
        int navail = negtake < negwin ? negtake : negwin;
        int filled = nsel + navail;
        for (int j = filled + tid; j < KOUT; j += 768) {
            ((float4*)out)[b * KOUT + j] = make_float4(0.f, 0.f, 0.f, 0.f);
            out[BB * KOUT * 4 + b * KOUT + j] = 0.f;
            ((float4*)(out + BB * KOUT * 4 + BB * KOUT))[b * KOUT + j] =
                make_float4(0.f, 0.f, 0.f, 0.f);
            out[BB * KOUT * 4 + BB * KOUT + BB * KOUT * 4 + b * KOUT + j] = 0.f;
        }
    }
}

extern "C" void kernel_launch(void* const* d_in, const int* in_sizes, int n_in,
                              void* d_out, int out_size) {
    const float4* boxes  = (const float4*)d_in[0];
    const float4* gts    = (const float4*)d_in[1];
    const int*    labels = (const int*)d_in[2];
    const float*  noise  = (const float*)d_in[3];
    float* out = (float*)d_out;

    k_iou<<<BB * CHUNKS, 128>>>(boxes, gts, noise);
    k_sortemit<<<dim3(BB, SORT_SLICES), 768>>>(boxes, gts, labels, out);
}